// round 6
// baseline (speedup 1.0000x reference)
#include <cuda_runtime.h>
#include <cstdint>

#define B_  8
#define S_  2048
#define D_  768
#define M1  (B_ * S_)

#define BM 128
#define BN 128
#define BK 16
#define STAGES 4
#define ASTRIDE 20          // [m][k] pad: banks 4g+t conflict-free
#define BSTRIDE_T 20        // BTRANS: [n][k]
#define BSTRIDE_N 136       // !BTRANS: [k][n] pad: banks 8t+g conflict-free
#define ASZ (BM * ASTRIDE)          // 2560 floats
#define BSZ_T (BN * BSTRIDE_T)      // 2560
#define BSZ_N (BK * BSTRIDE_N)      // 2176

// ---------------- scratch ----------------
__device__ float g_Q[(size_t)M1 * D_];   // stored tf32-rounded
__device__ float g_K[(size_t)M1 * D_];   // stored tf32-rounded
__device__ float g_V[(size_t)M1 * D_];   // stored tf32-rounded
__device__ float g_S[(size_t)B_ * S_ * S_];  // probs stored tf32-rounded

// ---------------- JAX threefry2x32 (bit-exact, verified R1) ----------------
__device__ __forceinline__ uint32_t rotl32(uint32_t x, uint32_t d) {
    return (x << d) | (x >> (32u - d));
}
__device__ __forceinline__ float tf_uniform(uint32_t idx) {
    const uint32_t K0 = 0u, K1 = 42u, K2 = 0x1BD11BDAu ^ 42u;
    uint32_t x0 = 0u + K0, x1 = idx + K1;
#define TF_R4(a,b,c,d) \
    x0 += x1; x1 = rotl32(x1,(a)); x1 ^= x0; \
    x0 += x1; x1 = rotl32(x1,(b)); x1 ^= x0; \
    x0 += x1; x1 = rotl32(x1,(c)); x1 ^= x0; \
    x0 += x1; x1 = rotl32(x1,(d)); x1 ^= x0;
    TF_R4(13,15,26, 6)  x0 += K1; x1 += K2 + 1u;
    TF_R4(17,29,16,24)  x0 += K2; x1 += K0 + 2u;
    TF_R4(13,15,26, 6)  x0 += K0; x1 += K1 + 3u;
    TF_R4(17,29,16,24)  x0 += K1; x1 += K2 + 4u;
    TF_R4(13,15,26, 6)  x0 += K2; x1 += K0 + 5u;
#undef TF_R4
    uint32_t bits = x0 ^ x1;
    return __uint_as_float((bits >> 9) | 0x3f800000u) - 1.0f;
}

// ---------------- tf32 / cp.async helpers ----------------
__device__ __forceinline__ uint32_t f2tf(float f) {
    uint32_t r;
    asm("cvt.rna.tf32.f32 %0, %1;" : "=r"(r) : "f"(f));
    return r;
}
__device__ __forceinline__ float f2tf_f(float f) {
    return __uint_as_float(f2tf(f));
}
__device__ __forceinline__ void mma_tf32(float (&c)[4], const uint32_t (&a)[4],
                                         const uint32_t (&b)[2]) {
    asm volatile(
        "mma.sync.aligned.m16n8k8.row.col.f32.tf32.tf32.f32 "
        "{%0,%1,%2,%3}, {%4,%5,%6,%7}, {%8,%9}, {%0,%1,%2,%3};"
        : "+f"(c[0]), "+f"(c[1]), "+f"(c[2]), "+f"(c[3])
        : "r"(a[0]), "r"(a[1]), "r"(a[2]), "r"(a[3]), "r"(b[0]), "r"(b[1]));
}
__device__ __forceinline__ void cpa16(uint32_t sa, const void* g) {
    asm volatile("cp.async.cg.shared.global [%0], [%1], 16;" :: "r"(sa), "l"(g));
}
__device__ __forceinline__ void cpa_commit() {
    asm volatile("cp.async.commit_group;");
}
template <int N>
__device__ __forceinline__ void cpa_wait() {
    asm volatile("cp.async.wait_group %0;" :: "n"(N));
}

// ---------------- pipelined tf32 MMA GEMM body ----------------
// 256 threads, block tile 128x128, 8 warps in 2x4, warp tile 64x32.
// A row-major M x K. B: BTRANS ? row-major N x K : row-major K x N (ldb).
// CVT: tf32-round at fragment load (only for external raw-fp32 operands).
template <bool BTRANS, bool CVT>
__device__ __forceinline__ void gemm_mma(const float* __restrict__ A,
                                         const float* __restrict__ Bm,
                                         int K, int ldb,
                                         float (&acc)[4][4][4]) {
    extern __shared__ float sm[];
    const int SS = ASZ + (BTRANS ? BSZ_T : BSZ_N);
    const uint32_t sbase = (uint32_t)__cvta_generic_to_shared(sm);

    const int tid  = threadIdx.x;
    const int row0 = blockIdx.y * BM;
    const int col0 = blockIdx.x * BN;
    const int lane = tid & 31, warp = tid >> 5;
    const int wm = (warp & 1) * 64;
    const int wn = (warp >> 1) * 32;
    const int g = lane >> 2, t = lane & 3;

#pragma unroll
    for (int mi = 0; mi < 4; ++mi)
#pragma unroll
        for (int ni = 0; ni < 4; ++ni)
#pragma unroll
            for (int q = 0; q < 4; ++q) acc[mi][ni][q] = 0.0f;

    auto load_stage = [&](int s, int it) {
        const int k0 = it * BK;
        const uint32_t st = sbase + (uint32_t)(s * SS) * 4u;
#pragma unroll
        for (int p = 0; p < 2; ++p) {
            const int c  = tid + (p << 8);
            const int r  = c >> 2;
            const int kc = (c & 3) << 2;
            cpa16(st + (uint32_t)(r * ASTRIDE + kc) * 4u,
                  A + (size_t)(row0 + r) * K + k0 + kc);
        }
        if (BTRANS) {
#pragma unroll
            for (int p = 0; p < 2; ++p) {
                const int c  = tid + (p << 8);
                const int r  = c >> 2;
                const int kc = (c & 3) << 2;
                cpa16(st + (uint32_t)(ASZ + r * BSTRIDE_T + kc) * 4u,
                      Bm + (size_t)(col0 + r) * ldb + k0 + kc);
            }
        } else {
#pragma unroll
            for (int p = 0; p < 2; ++p) {
                const int c  = tid + (p << 8);
                const int kr = c >> 5;
                const int nc = (c & 31) << 2;
                cpa16(st + (uint32_t)(ASZ + kr * BSTRIDE_N + nc) * 4u,
                      Bm + (size_t)(k0 + kr) * ldb + col0 + nc);
            }
        }
    };

    const int nk = K / BK;

#pragma unroll
    for (int p = 0; p < STAGES - 1; ++p) {
        load_stage(p, p);
        cpa_commit();
    }

    for (int i = 0; i < nk; ++i) {
        cpa_wait<STAGES - 2>();
        __syncthreads();

        const int ld = i + STAGES - 1;
        if (ld < nk) load_stage(ld & (STAGES - 1), ld);
        cpa_commit();

        const float* As = sm + (i & (STAGES - 1)) * SS;
        const float* Bs = As + ASZ;
#pragma unroll
        for (int ks = 0; ks < BK / 8; ++ks) {
            const int k = ks << 3;
            uint32_t a[4][4];
#pragma unroll
            for (int mi = 0; mi < 4; ++mi) {
                const int m = wm + (mi << 4);
                float a0 = As[(m + g    ) * ASTRIDE + k + t    ];
                float a1 = As[(m + g + 8) * ASTRIDE + k + t    ];
                float a2 = As[(m + g    ) * ASTRIDE + k + t + 4];
                float a3 = As[(m + g + 8) * ASTRIDE + k + t + 4];
                a[mi][0] = CVT ? f2tf(a0) : __float_as_uint(a0);
                a[mi][1] = CVT ? f2tf(a1) : __float_as_uint(a1);
                a[mi][2] = CVT ? f2tf(a2) : __float_as_uint(a2);
                a[mi][3] = CVT ? f2tf(a3) : __float_as_uint(a3);
            }
            uint32_t b[4][2];
#pragma unroll
            for (int ni = 0; ni < 4; ++ni) {
                const int n = wn + (ni << 3);
                float b0, b1;
                if (BTRANS) {
                    b0 = Bs[(n + g) * BSTRIDE_T + k + t    ];
                    b1 = Bs[(n + g) * BSTRIDE_T + k + t + 4];
                } else {
                    b0 = Bs[(k + t    ) * BSTRIDE_N + n + g];
                    b1 = Bs[(k + t + 4) * BSTRIDE_N + n + g];
                }
                b[ni][0] = CVT ? f2tf(b0) : __float_as_uint(b0);
                b[ni][1] = CVT ? f2tf(b1) : __float_as_uint(b1);
            }
#pragma unroll
            for (int mi = 0; mi < 4; ++mi)
#pragma unroll
                for (int ni = 0; ni < 4; ++ni)
                    mma_tf32(acc[mi][ni], a[mi], b[ni]);
        }
    }
    cpa_wait<0>();
}

// ---------------- kernel 1: fused Q/K/V projections ----------------
struct ProjArgs {
    const float* X[3];
    const float* W[3];
    const float* b[3];
    float*       C[3];
};

__global__ __launch_bounds__(256, 2)
void proj_kernel(ProjArgs pa) {
    const int z = blockIdx.z;
    float acc[4][4][4];
    gemm_mma<false, true>(pa.X[z], pa.W[z], D_, D_, acc);

    const float* bias = pa.b[z];
    float* C = pa.C[z];
    const int tid = threadIdx.x, lane = tid & 31, warp = tid >> 5;
    const int row0 = blockIdx.y * BM + (warp & 1) * 64 + (lane >> 2);
    const int col0 = blockIdx.x * BN + (warp >> 1) * 32 + (lane & 3) * 2;
    // store tf32-rounded so downstream GEMMs skip cvt (bit-identical numerics)
#pragma unroll
    for (int mi = 0; mi < 4; ++mi) {
#pragma unroll
        for (int ni = 0; ni < 4; ++ni) {
            const int c = col0 + (ni << 3);
            const float bx = __ldg(bias + c), by = __ldg(bias + c + 1);
            const int r1 = row0 + (mi << 4);
            float2 o0 = make_float2(f2tf_f(acc[mi][ni][0] + bx),
                                    f2tf_f(acc[mi][ni][1] + by));
            float2 o1 = make_float2(f2tf_f(acc[mi][ni][2] + bx),
                                    f2tf_f(acc[mi][ni][3] + by));
            *reinterpret_cast<float2*>(C + (size_t)r1 * D_ + c)       = o0;
            *reinterpret_cast<float2*>(C + (size_t)(r1 + 8) * D_ + c) = o1;
        }
    }
}

// ------- kernel 2: scores = (Q K^T)/sqrt(D) + pre-softmax dropout -------
__global__ __launch_bounds__(256, 2)
void scores_kernel() {
    const int bz = blockIdx.z;
    const float* A  = g_Q + (size_t)bz * S_ * D_;
    const float* Bm = g_K + (size_t)bz * S_ * D_;
    float* C = g_S + (size_t)bz * S_ * S_;
    float acc[4][4][4];
    gemm_mma<true, false>(A, Bm, D_, D_, acc);

    const int tid = threadIdx.x, lane = tid & 31, warp = tid >> 5;
    const int row0 = blockIdx.y * BM + (warp & 1) * 64 + (lane >> 2);
    const int col0 = blockIdx.x * BN + (warp >> 1) * 32 + (lane & 3) * 2;
    const float sc = 0.03608439182435161f;  // 1/sqrt(768)
#pragma unroll
    for (int mi = 0; mi < 4; ++mi) {
#pragma unroll
        for (int rr = 0; rr < 2; ++rr) {
            const int r = row0 + (mi << 4) + (rr << 3);
            const uint32_t ib = ((uint32_t)bz * S_ + (uint32_t)r) * (uint32_t)S_;
#pragma unroll
            for (int ni = 0; ni < 4; ++ni) {
                const int c = col0 + (ni << 3);
                const float v0 = acc[mi][ni][rr * 2 + 0] * sc;
                const float v1 = acc[mi][ni][rr * 2 + 1] * sc;
                const float u0 = tf_uniform(ib + (uint32_t)c);
                const float u1 = tf_uniform(ib + (uint32_t)c + 1u);
                float2 o;
                o.x = (u0 < 0.8f) ? v0 * 1.25f : 0.0f;
                o.y = (u1 < 0.8f) ? v1 * 1.25f : 0.0f;
                *reinterpret_cast<float2*>(C + (size_t)r * S_ + c) = o;
            }
        }
    }
}

// -------- kernel 3: softmax over k, then post-softmax mask -> 1e-9 --------
__global__ __launch_bounds__(256)
void softmax_mask_kernel(const int* __restrict__ mask) {
    const int row = blockIdx.x;
    float* srow = g_S + (size_t)row * S_;
    const int* mrow = mask + (size_t)row * S_;
    const int t = threadIdx.x;
    __shared__ float red[8];

    float4 v4[2];
    v4[0] = *reinterpret_cast<const float4*>(srow + (t << 2));
    v4[1] = *reinterpret_cast<const float4*>(srow + 1024 + (t << 2));
    float* v = reinterpret_cast<float*>(v4);

    float mx = v[0];
#pragma unroll
    for (int i = 1; i < 8; ++i) mx = fmaxf(mx, v[i]);
#pragma unroll
    for (int o = 16; o > 0; o >>= 1)
        mx = fmaxf(mx, __shfl_xor_sync(0xffffffffu, mx, o));
    if ((t & 31) == 0) red[t >> 5] = mx;
    __syncthreads();
    if (t < 32) {
        float m2 = (t < 8) ? red[t] : -3.4e38f;
#pragma unroll
        for (int o = 4; o > 0; o >>= 1)
            m2 = fmaxf(m2, __shfl_xor_sync(0xffffffffu, m2, o));
        if (t == 0) red[0] = m2;
    }
    __syncthreads();
    mx = red[0];
    __syncthreads();

    float sum = 0.0f;
#pragma unroll
    for (int i = 0; i < 8; ++i) { v[i] = __expf(v[i] - mx); sum += v[i]; }
#pragma unroll
    for (int o = 16; o > 0; o >>= 1)
        sum += __shfl_xor_sync(0xffffffffu, sum, o);
    if ((t & 31) == 0) red[t >> 5] = sum;
    __syncthreads();
    if (t < 32) {
        float s2 = (t < 8) ? red[t] : 0.0f;
#pragma unroll
        for (int o = 4; o > 0; o >>= 1)
            s2 += __shfl_xor_sync(0xffffffffu, s2, o);
        if (t == 0) red[0] = s2;
    }
    __syncthreads();
    const float inv = 1.0f / red[0];

    int4 m4[2];
    m4[0] = *reinterpret_cast<const int4*>(mrow + (t << 2));
    m4[1] = *reinterpret_cast<const int4*>(mrow + 1024 + (t << 2));
    const int* m = reinterpret_cast<const int*>(m4);
    // store tf32-rounded probs so out_kernel skips cvt (bit-identical numerics)
#pragma unroll
    for (int i = 0; i < 8; ++i)
        v[i] = (m[i] == 0) ? f2tf_f(1e-9f) : f2tf_f(v[i] * inv);
    *reinterpret_cast<float4*>(srow + (t << 2))        = v4[0];
    *reinterpret_cast<float4*>(srow + 1024 + (t << 2)) = v4[1];
}

// ---------------- kernel 4: out = att @ V ----------------
__global__ __launch_bounds__(256, 2)
void out_kernel(float* __restrict__ Og) {
    const int bz = blockIdx.z;
    const float* A  = g_S + (size_t)bz * S_ * S_;
    const float* Bm = g_V + (size_t)bz * S_ * D_;
    float* C = Og + (size_t)bz * S_ * D_;
    float acc[4][4][4];
    gemm_mma<false, false>(A, Bm, S_, D_, acc);

    const int tid = threadIdx.x, lane = tid & 31, warp = tid >> 5;
    const int row0 = blockIdx.y * BM + (warp & 1) * 64 + (lane >> 2);
    const int col0 = blockIdx.x * BN + (warp >> 1) * 32 + (lane & 3) * 2;
#pragma unroll
    for (int mi = 0; mi < 4; ++mi) {
#pragma unroll
        for (int ni = 0; ni < 4; ++ni) {
            const int c = col0 + (ni << 3);
            const int r1 = row0 + (mi << 4);
            float2 o0 = make_float2(acc[mi][ni][0], acc[mi][ni][1]);
            float2 o1 = make_float2(acc[mi][ni][2], acc[mi][ni][3]);
            *reinterpret_cast<float2*>(C + (size_t)r1 * D_ + c)       = o0;
            *reinterpret_cast<float2*>(C + (size_t)(r1 + 8) * D_ + c) = o1;
        }
    }
}

// ---------------- launch ----------------
extern "C" void kernel_launch(void* const* d_in, const int* in_sizes, int n_in,
                              void* d_out, int out_size) {
    const float* q    = (const float*)d_in[0];
    const float* k    = (const float*)d_in[1];
    const float* v    = (const float*)d_in[2];
    const int*   mask = (const int*)  d_in[3];

    float *Qp, *Kp, *Vp;
    cudaGetSymbolAddress((void**)&Qp, g_Q);
    cudaGetSymbolAddress((void**)&Kp, g_K);
    cudaGetSymbolAddress((void**)&Vp, g_V);

    ProjArgs pa;
    pa.X[0] = q; pa.X[1] = k; pa.X[2] = v;
    pa.W[0] = (const float*)d_in[4]; pa.b[0] = (const float*)d_in[5];
    pa.W[1] = (const float*)d_in[6]; pa.b[1] = (const float*)d_in[7];
    pa.W[2] = (const float*)d_in[8]; pa.b[2] = (const float*)d_in[9];
    pa.C[0] = Qp; pa.C[1] = Kp; pa.C[2] = Vp;

    const int smem_n = (ASZ + BSZ_N) * 4 * STAGES;  // 75776 B
    const int smem_t = (ASZ + BSZ_T) * 4 * STAGES;  // 81920 B
    cudaFuncSetAttribute(proj_kernel,
        cudaFuncAttributeMaxDynamicSharedMemorySize, smem_n);
    cudaFuncSetAttribute(scores_kernel,
        cudaFuncAttributeMaxDynamicSharedMemorySize, smem_t);
    cudaFuncSetAttribute(out_kernel,
        cudaFuncAttributeMaxDynamicSharedMemorySize, smem_n);

    dim3 blk(256);
    dim3 gproj(D_ / BN, M1 / BM, 3);
    proj_kernel<<<gproj, blk, smem_n>>>(pa);

    dim3 gsc(S_ / BN, S_ / BM, B_);
    scores_kernel<<<gsc, blk, smem_t>>>();

    softmax_mask_kernel<<<M1, 256>>>(mask);

    dim3 gout(D_ / BN, S_ / BM, B_);
    out_kernel<<<gout, blk, smem_n>>>((float*)d_out);
}

// round 10
// speedup vs baseline: 2.0595x; 2.0595x over previous
#include <cuda_runtime.h>
#include <cuda_fp16.h>
#include <cstdint>

#define B_  8
#define S_  2048
#define D_  768
#define M1  (B_ * S_)

// ---------------- fp32 tf32 proj GEMM config (R3-proven) ----------------
#define BM 128
#define BN 128
#define BK 16
#define STAGES 4
#define ASTRIDE 20
#define BSTRIDE_N 136
#define ASZ (BM * ASTRIDE)
#define BSZ_N (BK * BSTRIDE_N)

// ---------------- fp16 GEMM config ----------------
#define HBK 32                 // halves per k-tile
#define HSTRIDE 40             // halves per row in smem (pad 32->40)
#define HST 4
#define H_A_BYTES (BM * HSTRIDE * 2)   // 10240
#define H_STAGE_BYTES (2 * H_A_BYTES)  // A + B = 20480

// ---------------- scratch ----------------
__device__ __half g_Qh [(size_t)M1 * D_];
__device__ __half g_Kh [(size_t)M1 * D_];
__device__ __half g_Vh [(size_t)M1 * D_];
__device__ __half g_Vth[(size_t)B_ * D_ * S_];     // V transposed [b][d][s]
__device__ float  g_S  [(size_t)B_ * S_ * S_];     // raw scores fp32
__device__ __half g_P  [(size_t)B_ * S_ * S_];     // probs fp16

// ---------------- JAX threefry2x32 (bit-exact, verified R1) ----------------
__device__ __forceinline__ uint32_t rotl32(uint32_t x, uint32_t d) {
    return (x << d) | (x >> (32u - d));
}
__device__ __forceinline__ float tf_uniform(uint32_t idx) {
    const uint32_t K0 = 0u, K1 = 42u, K2 = 0x1BD11BDAu ^ 42u;
    uint32_t x0 = 0u + K0, x1 = idx + K1;
#define TF_R4(a,b,c,d) \
    x0 += x1; x1 = rotl32(x1,(a)); x1 ^= x0; \
    x0 += x1; x1 = rotl32(x1,(b)); x1 ^= x0; \
    x0 += x1; x1 = rotl32(x1,(c)); x1 ^= x0; \
    x0 += x1; x1 = rotl32(x1,(d)); x1 ^= x0;
    TF_R4(13,15,26, 6)  x0 += K1; x1 += K2 + 1u;
    TF_R4(17,29,16,24)  x0 += K2; x1 += K0 + 2u;
    TF_R4(13,15,26, 6)  x0 += K0; x1 += K1 + 3u;
    TF_R4(17,29,16,24)  x0 += K1; x1 += K2 + 4u;
    TF_R4(13,15,26, 6)  x0 += K2; x1 += K0 + 5u;
#undef TF_R4
    uint32_t bits = x0 ^ x1;
    return __uint_as_float((bits >> 9) | 0x3f800000u) - 1.0f;
}

// ---------------- helpers ----------------
__device__ __forceinline__ uint32_t f2tf(float f) {
    uint32_t r;
    asm("cvt.rna.tf32.f32 %0, %1;" : "=r"(r) : "f"(f));
    return r;
}
__device__ __forceinline__ void mma_tf32(float (&c)[4], const uint32_t (&a)[4],
                                         const uint32_t (&b)[2]) {
    asm volatile(
        "mma.sync.aligned.m16n8k8.row.col.f32.tf32.tf32.f32 "
        "{%0,%1,%2,%3}, {%4,%5,%6,%7}, {%8,%9}, {%0,%1,%2,%3};"
        : "+f"(c[0]), "+f"(c[1]), "+f"(c[2]), "+f"(c[3])
        : "r"(a[0]), "r"(a[1]), "r"(a[2]), "r"(a[3]), "r"(b[0]), "r"(b[1]));
}
__device__ __forceinline__ void mma_f16(float (&c)[4], const uint32_t (&a)[4],
                                        const uint32_t (&b)[2]) {
    asm volatile(
        "mma.sync.aligned.m16n8k16.row.col.f32.f16.f16.f32 "
        "{%0,%1,%2,%3}, {%4,%5,%6,%7}, {%8,%9}, {%0,%1,%2,%3};"
        : "+f"(c[0]), "+f"(c[1]), "+f"(c[2]), "+f"(c[3])
        : "r"(a[0]), "r"(a[1]), "r"(a[2]), "r"(a[3]), "r"(b[0]), "r"(b[1]));
}
__device__ __forceinline__ void cpa16(uint32_t sa, const void* g) {
    asm volatile("cp.async.cg.shared.global [%0], [%1], 16;" :: "r"(sa), "l"(g));
}
__device__ __forceinline__ void cpa_commit() {
    asm volatile("cp.async.commit_group;");
}
template <int N>
__device__ __forceinline__ void cpa_wait() {
    asm volatile("cp.async.wait_group %0;" :: "n"(N));
}

// ============ fp32->tf32 pipelined GEMM (proj only): C = A @ B, B is KxN ====
__device__ __forceinline__ void gemm_proj(const float* __restrict__ A,
                                          const float* __restrict__ Bm,
                                          float (&acc)[4][4][4]) {
    extern __shared__ float sm[];
    const int SS = ASZ + BSZ_N;
    const uint32_t sbase = (uint32_t)__cvta_generic_to_shared(sm);
    const int tid  = threadIdx.x;
    const int row0 = blockIdx.y * BM;
    const int col0 = blockIdx.x * BN;
    const int lane = tid & 31, warp = tid >> 5;
    const int wm = (warp & 1) * 64;
    const int wn = (warp >> 1) * 32;
    const int g = lane >> 2, t = lane & 3;

#pragma unroll
    for (int mi = 0; mi < 4; ++mi)
#pragma unroll
        for (int ni = 0; ni < 4; ++ni)
#pragma unroll
            for (int q = 0; q < 4; ++q) acc[mi][ni][q] = 0.0f;

    auto load_stage = [&](int s, int it) {
        const int k0 = it * BK;
        const uint32_t st = sbase + (uint32_t)(s * SS) * 4u;
#pragma unroll
        for (int p = 0; p < 2; ++p) {
            const int c  = tid + (p << 8);
            const int r  = c >> 2;
            const int kc = (c & 3) << 2;
            cpa16(st + (uint32_t)(r * ASTRIDE + kc) * 4u,
                  A + (size_t)(row0 + r) * D_ + k0 + kc);
        }
#pragma unroll
        for (int p = 0; p < 2; ++p) {
            const int c  = tid + (p << 8);
            const int kr = c >> 5;
            const int nc = (c & 31) << 2;
            cpa16(st + (uint32_t)(ASZ + kr * BSTRIDE_N + nc) * 4u,
                  Bm + (size_t)(k0 + kr) * D_ + col0 + nc);
        }
    };

    const int nk = D_ / BK;
#pragma unroll
    for (int p = 0; p < STAGES - 1; ++p) { load_stage(p, p); cpa_commit(); }

    for (int i = 0; i < nk; ++i) {
        cpa_wait<STAGES - 2>();
        __syncthreads();
        const int ld = i + STAGES - 1;
        if (ld < nk) load_stage(ld & (STAGES - 1), ld);
        cpa_commit();

        const float* As = sm + (i & (STAGES - 1)) * SS;
        const float* Bs = As + ASZ;
#pragma unroll
        for (int ks = 0; ks < BK / 8; ++ks) {
            const int k = ks << 3;
            uint32_t a[4][4];
#pragma unroll
            for (int mi = 0; mi < 4; ++mi) {
                const int m = wm + (mi << 4);
                a[mi][0] = f2tf(As[(m + g    ) * ASTRIDE + k + t    ]);
                a[mi][1] = f2tf(As[(m + g + 8) * ASTRIDE + k + t    ]);
                a[mi][2] = f2tf(As[(m + g    ) * ASTRIDE + k + t + 4]);
                a[mi][3] = f2tf(As[(m + g + 8) * ASTRIDE + k + t + 4]);
            }
            uint32_t b[4][2];
#pragma unroll
            for (int ni = 0; ni < 4; ++ni) {
                const int n = wn + (ni << 3);
                b[ni][0] = f2tf(Bs[(k + t    ) * BSTRIDE_N + n + g]);
                b[ni][1] = f2tf(Bs[(k + t + 4) * BSTRIDE_N + n + g]);
            }
#pragma unroll
            for (int mi = 0; mi < 4; ++mi)
#pragma unroll
                for (int ni = 0; ni < 4; ++ni)
                    mma_tf32(acc[mi][ni], a[mi], b[ni]);
        }
    }
    cpa_wait<0>();
}

// ============ fp16 pipelined GEMM: C = A @ B^T, A [M][K], B [N][K] halves ===
__device__ __forceinline__ void gemm_h(const __half* __restrict__ A,
                                       const __half* __restrict__ Bm,
                                       int K, int row0, int col0,
                                       float (&acc)[4][4][4]) {
    extern __shared__ float smf[];
    __half* sm = reinterpret_cast<__half*>(smf);
    const uint32_t sbase = (uint32_t)__cvta_generic_to_shared(sm);
    const int tid  = threadIdx.x;
    const int lane = tid & 31, warp = tid >> 5;
    const int wm = (warp & 1) * 64;
    const int wn = (warp >> 1) * 32;
    const int g = lane >> 2, t = lane & 3;

#pragma unroll
    for (int mi = 0; mi < 4; ++mi)
#pragma unroll
        for (int ni = 0; ni < 4; ++ni)
#pragma unroll
            for (int q = 0; q < 4; ++q) acc[mi][ni][q] = 0.0f;

    // stage layout (halves): A[128][HSTRIDE] then B[128][HSTRIDE]
    auto load_stage = [&](int s, int it) {
        const int k0 = it * HBK;
        const uint32_t st = sbase + (uint32_t)s * H_STAGE_BYTES;
#pragma unroll
        for (int p = 0; p < 2; ++p) {           // A: 128 rows x 4 chunks(8 halves)
            const int c  = tid + (p << 8);
            const int r  = c >> 2;
            const int ch = c & 3;
            cpa16(st + (uint32_t)(r * HSTRIDE + ch * 8) * 2u,
                  A + (size_t)(row0 + r) * K + k0 + ch * 8);
        }
#pragma unroll
        for (int p = 0; p < 2; ++p) {           // B: 128 rows x 4 chunks
            const int c  = tid + (p << 8);
            const int r  = c >> 2;
            const int ch = c & 3;
            cpa16(st + H_A_BYTES + (uint32_t)(r * HSTRIDE + ch * 8) * 2u,
                  Bm + (size_t)(col0 + r) * K + k0 + ch * 8);
        }
    };

    const int nk = K / HBK;
#pragma unroll
    for (int p = 0; p < HST - 1; ++p) { load_stage(p, p); cpa_commit(); }

    for (int i = 0; i < nk; ++i) {
        cpa_wait<HST - 2>();
        __syncthreads();
        const int ld = i + HST - 1;
        if (ld < nk) load_stage(ld & (HST - 1), ld);
        cpa_commit();

        const __half* As = sm + (size_t)(i & (HST - 1)) * (H_STAGE_BYTES / 2);
        const __half* Bs = As + BM * HSTRIDE;
#pragma unroll
        for (int ks = 0; ks < HBK / 16; ++ks) {
            const int k = ks << 4;
            uint32_t a[4][4];
#pragma unroll
            for (int mi = 0; mi < 4; ++mi) {
                const int m = wm + (mi << 4);
                a[mi][0] = *reinterpret_cast<const uint32_t*>(
                    &As[(m + g    ) * HSTRIDE + k + t * 2]);
                a[mi][1] = *reinterpret_cast<const uint32_t*>(
                    &As[(m + g + 8) * HSTRIDE + k + t * 2]);
                a[mi][2] = *reinterpret_cast<const uint32_t*>(
                    &As[(m + g    ) * HSTRIDE + k + 8 + t * 2]);
                a[mi][3] = *reinterpret_cast<const uint32_t*>(
                    &As[(m + g + 8) * HSTRIDE + k + 8 + t * 2]);
            }
            uint32_t b[4][2];
#pragma unroll
            for (int ni = 0; ni < 4; ++ni) {
                const int n = wn + (ni << 3);
                b[ni][0] = *reinterpret_cast<const uint32_t*>(
                    &Bs[(n + g) * HSTRIDE + k + t * 2]);
                b[ni][1] = *reinterpret_cast<const uint32_t*>(
                    &Bs[(n + g) * HSTRIDE + k + 8 + t * 2]);
            }
#pragma unroll
            for (int mi = 0; mi < 4; ++mi)
#pragma unroll
                for (int ni = 0; ni < 4; ++ni)
                    mma_f16(acc[mi][ni], a[mi], b[ni]);
        }
    }
    cpa_wait<0>();
}

// ---------------- kernel 1: fused Q/K/V projections -> fp16 ----------------
struct ProjArgs {
    const float* X[3];
    const float* W[3];
    const float* b[3];
};

__global__ __launch_bounds__(256, 2)
void proj_kernel(ProjArgs pa) {
    const int z = blockIdx.z;
    float acc[4][4][4];
    gemm_proj(pa.X[z], pa.W[z], acc);

    const float* bias = pa.b[z];
    __half* C = (z == 0) ? g_Qh : (z == 1) ? g_Kh : g_Vh;
    const int tid = threadIdx.x, lane = tid & 31, warp = tid >> 5;
    const int row0 = blockIdx.y * BM + (warp & 1) * 64 + (lane >> 2);
    const int col0 = blockIdx.x * BN + (warp >> 1) * 32 + (lane & 3) * 2;
#pragma unroll
    for (int mi = 0; mi < 4; ++mi) {
#pragma unroll
        for (int ni = 0; ni < 4; ++ni) {
            const int c = col0 + (ni << 3);
            const float bx = __ldg(bias + c), by = __ldg(bias + c + 1);
            const int r1 = row0 + (mi << 4);
            __half2 h0 = __floats2half2_rn(acc[mi][ni][0] + bx, acc[mi][ni][1] + by);
            __half2 h1 = __floats2half2_rn(acc[mi][ni][2] + bx, acc[mi][ni][3] + by);
            *reinterpret_cast<__half2*>(C + (size_t)r1 * D_ + c)       = h0;
            *reinterpret_cast<__half2*>(C + (size_t)(r1 + 8) * D_ + c) = h1;
        }
    }
}

// ---------------- kernel 1b: transpose V (fp16) [b][s][d] -> [b][d][s] -----
__global__ __launch_bounds__(256)
void transpose_v_kernel() {
    __shared__ __half tile[64][65];
    const int b = blockIdx.z;
    const int s0 = blockIdx.x * 64, d0 = blockIdx.y * 64;
    const __half* in = g_Vh + (size_t)b * S_ * D_;
    __half* out = g_Vth + (size_t)b * D_ * S_;
    const int tid = threadIdx.x;
#pragma unroll
    for (int i = 0; i < 16; ++i) {
        const int idx = tid + (i << 8);
        const int r = idx >> 6, c = idx & 63;
        tile[r][c] = in[(size_t)(s0 + r) * D_ + d0 + c];
    }
    __syncthreads();
#pragma unroll
    for (int i = 0; i < 16; ++i) {
        const int idx = tid + (i << 8);
        const int r = idx >> 6, c = idx & 63;
        out[(size_t)(d0 + r) * S_ + s0 + c] = tile[c][r];
    }
}

// ------- kernel 2: scores = (Q K^T)/sqrt(D) + pre-softmax dropout (fp32 out)
__global__ __launch_bounds__(256, 2)
void scores_kernel() {
    const int bz = blockIdx.z;
    const int row0 = blockIdx.y * BM, col0 = blockIdx.x * BN;
    float acc[4][4][4];
    gemm_h(g_Qh + (size_t)bz * S_ * D_, g_Kh + (size_t)bz * S_ * D_,
           D_, row0, col0, acc);

    float* C = g_S + (size_t)bz * S_ * S_;
    const int tid = threadIdx.x, lane = tid & 31, warp = tid >> 5;
    const int rw0 = row0 + (warp & 1) * 64 + (lane >> 2);
    const int cw0 = col0 + (warp >> 1) * 32 + (lane & 3) * 2;
    const float sc = 0.03608439182435161f;  // 1/sqrt(768)
#pragma unroll
    for (int mi = 0; mi < 4; ++mi) {
#pragma unroll
        for (int rr = 0; rr < 2; ++rr) {
            const int r = rw0 + (mi << 4) + (rr << 3);
            const uint32_t ib = ((uint32_t)bz * S_ + (uint32_t)r) * (uint32_t)S_;
#pragma unroll
            for (int ni = 0; ni < 4; ++ni) {
                const int c = cw0 + (ni << 3);
                const float v0 = acc[mi][ni][rr * 2 + 0] * sc;
                const float v1 = acc[mi][ni][rr * 2 + 1] * sc;
                const float u0 = tf_uniform(ib + (uint32_t)c);
                const float u1 = tf_uniform(ib + (uint32_t)c + 1u);
                float2 o;
                o.x = (u0 < 0.8f) ? v0 * 1.25f : 0.0f;
                o.y = (u1 < 0.8f) ? v1 * 1.25f : 0.0f;
                *reinterpret_cast<float2*>(C + (size_t)r * S_ + c) = o;
            }
        }
    }
}

// ------ kernel 3: softmax over k, post-softmax mask, write fp16 probs ------
__global__ __launch_bounds__(256)
void softmax_mask_kernel(const int* __restrict__ mask) {
    const int row = blockIdx.x;
    const float* srow = g_S + (size_t)row * S_;
    __half* prow = g_P + (size_t)row * S_;
    const int* mrow = mask + (size_t)row * S_;
    const int t = threadIdx.x;
    __shared__ float red[8];

    float4 v4[2];
    v4[0] = *reinterpret_cast<const float4*>(srow + (t << 2));
    v4[1] = *reinterpret_cast<const float4*>(srow + 1024 + (t << 2));
    float* v = reinterpret_cast<float*>(v4);

    float mx = v[0];
#pragma unroll
    for (int i = 1; i < 8; ++i) mx = fmaxf(mx, v[i]);
#pragma unroll
    for (int o = 16; o > 0; o >>= 1)
        mx = fmaxf(mx, __shfl_xor_sync(0xffffffffu, mx, o));
    if ((t & 31) == 0) red[t >> 5] = mx;
    __syncthreads();
    if (t < 32) {
        float m2 = (t < 8) ? red[t] : -3.4e38f;
#pragma unroll
        for (int o = 4; o > 0; o >>= 1)
            m2 = fmaxf(m2, __shfl_xor_sync(0xffffffffu, m2, o));
        if (t == 0) red[0] = m2;
    }
    __syncthreads();
    mx = red[0];
    __syncthreads();

    float sum = 0.0f;
#pragma unroll
    for (int i = 0; i < 8; ++i) { v[i] = __expf(v[i] - mx); sum += v[i]; }
#pragma unroll
    for (int o = 16; o > 0; o >>= 1)
        sum += __shfl_xor_sync(0xffffffffu, sum, o);
    if ((t & 31) == 0) red[t >> 5] = sum;
    __syncthreads();
    if (t < 32) {
        float s2 = (t < 8) ? red[t] : 0.0f;
#pragma unroll
        for (int o = 4; o > 0; o >>= 1)
            s2 += __shfl_xor_sync(0xffffffffu, s2, o);
        if (t == 0) red[0] = s2;
    }
    __syncthreads();
    const float inv = 1.0f / red[0];

    int4 m4[2];
    m4[0] = *reinterpret_cast<const int4*>(mrow + (t << 2));
    m4[1] = *reinterpret_cast<const int4*>(mrow + 1024 + (t << 2));
    const int* m = reinterpret_cast<const int*>(m4);
#pragma unroll
    for (int i = 0; i < 8; ++i)
        v[i] = (m[i] == 0) ? 1e-9f : v[i] * inv;
#pragma unroll
    for (int p = 0; p < 2; ++p) {
        __half2 h0 = __floats2half2_rn(v[p * 4 + 0], v[p * 4 + 1]);
        __half2 h1 = __floats2half2_rn(v[p * 4 + 2], v[p * 4 + 3]);
        const int base = p * 1024 + (t << 2);
        *reinterpret_cast<__half2*>(prow + base)     = h0;
        *reinterpret_cast<__half2*>(prow + base + 2) = h1;
    }
}

// -------- kernel 4: out = att @ V  (A = probs fp16, B = Vt fp16 BTRANS) ----
__global__ __launch_bounds__(256, 2)
void out_kernel(float* __restrict__ Og) {
    const int bz = blockIdx.z;
    const int row0 = blockIdx.y * BM, col0 = blockIdx.x * BN;
    float acc[4][4][4];
    gemm_h(g_P + (size_t)bz * S_ * S_, g_Vth + (size_t)bz * D_ * S_,
           S_, row0, col0, acc);

    float* C = Og + (size_t)bz * S_ * D_;
    const int tid = threadIdx.x, lane = tid & 31, warp = tid >> 5;
    const int rw0 = row0 + (warp & 1) * 64 + (lane >> 2);
    const int cw0 = col0 + (warp >> 1) * 32 + (lane & 3) * 2;
#pragma unroll
    for (int mi = 0; mi < 4; ++mi) {
#pragma unroll
        for (int ni = 0; ni < 4; ++ni) {
            const int c = cw0 + (ni << 3);
            const int r1 = rw0 + (mi << 4);
            float2 o0 = make_float2(acc[mi][ni][0], acc[mi][ni][1]);
            float2 o1 = make_float2(acc[mi][ni][2], acc[mi][ni][3]);
            *reinterpret_cast<float2*>(C + (size_t)r1 * D_ + c)       = o0;
            *reinterpret_cast<float2*>(C + (size_t)(r1 + 8) * D_ + c) = o1;
        }
    }
}

// ---------------- launch ----------------
extern "C" void kernel_launch(void* const* d_in, const int* in_sizes, int n_in,
                              void* d_out, int out_size) {
    const float* q    = (const float*)d_in[0];
    const float* k    = (const float*)d_in[1];
    const float* v    = (const float*)d_in[2];
    const int*   mask = (const int*)  d_in[3];

    ProjArgs pa;
    pa.X[0] = q; pa.X[1] = k; pa.X[2] = v;
    pa.W[0] = (const float*)d_in[4]; pa.b[0] = (const float*)d_in[5];
    pa.W[1] = (const float*)d_in[6]; pa.b[1] = (const float*)d_in[7];
    pa.W[2] = (const float*)d_in[8]; pa.b[2] = (const float*)d_in[9];

    const int smem_proj = (ASZ + BSZ_N) * 4 * STAGES;   // 75776 B
    const int smem_h    = H_STAGE_BYTES * HST;          // 81920 B
    cudaFuncSetAttribute(proj_kernel,
        cudaFuncAttributeMaxDynamicSharedMemorySize, smem_proj);
    cudaFuncSetAttribute(scores_kernel,
        cudaFuncAttributeMaxDynamicSharedMemorySize, smem_h);
    cudaFuncSetAttribute(out_kernel,
        cudaFuncAttributeMaxDynamicSharedMemorySize, smem_h);

    dim3 blk(256);

    dim3 gproj(D_ / BN, M1 / BM, 3);
    proj_kernel<<<gproj, blk, smem_proj>>>(pa);

    dim3 gtv(S_ / 64, D_ / 64, B_);
    transpose_v_kernel<<<gtv, blk>>>();

    dim3 gsc(S_ / BN, S_ / BM, B_);
    scores_kernel<<<gsc, blk, smem_h>>>();

    softmax_mask_kernel<<<M1, blk>>>(mask);

    dim3 gout(D_ / BN, S_ / BM, B_);
    out_kernel<<<gout, blk, smem_h>>>((float*)d_out);
}

// round 11
// speedup vs baseline: 2.3924x; 1.1616x over previous
#include <cuda_runtime.h>
#include <cuda_fp16.h>
#include <cstdint>

#define B_  8
#define S_  2048
#define D_  768
#define M1  (B_ * S_)

// ---------------- fp16 GEMM config ----------------
#define BM 128
#define BN 128
#define HBK 32                 // halves per k-tile
#define HSTRIDE 40             // halves per row in smem (pad 32->40)
#define HST 4
#define H_A_BYTES (BM * HSTRIDE * 2)   // 10240
#define H_STAGE_BYTES (2 * H_A_BYTES)  // A + B = 20480

// ---------------- scratch ----------------
__device__ __half g_Xh [3][(size_t)M1 * D_];       // fp16 inputs q,k,v
__device__ __half g_Wth[3][(size_t)D_ * D_];       // fp16 W transposed [n][k]
__device__ __half g_Qh [(size_t)M1 * D_];
__device__ __half g_Kh [(size_t)M1 * D_];
__device__ __half g_Vh [(size_t)M1 * D_];
__device__ __half g_Vth[(size_t)B_ * D_ * S_];     // V transposed [b][d][s]
__device__ float  g_S  [(size_t)B_ * S_ * S_];     // raw scores fp32
__device__ __half g_P  [(size_t)B_ * S_ * S_];     // probs fp16

// ---------------- JAX threefry2x32 (bit-exact, verified R1) ----------------
__device__ __forceinline__ uint32_t rotl32(uint32_t x, uint32_t d) {
    return (x << d) | (x >> (32u - d));
}
__device__ __forceinline__ float tf_uniform(uint32_t idx) {
    const uint32_t K0 = 0u, K1 = 42u, K2 = 0x1BD11BDAu ^ 42u;
    uint32_t x0 = 0u + K0, x1 = idx + K1;
#define TF_R4(a,b,c,d) \
    x0 += x1; x1 = rotl32(x1,(a)); x1 ^= x0; \
    x0 += x1; x1 = rotl32(x1,(b)); x1 ^= x0; \
    x0 += x1; x1 = rotl32(x1,(c)); x1 ^= x0; \
    x0 += x1; x1 = rotl32(x1,(d)); x1 ^= x0;
    TF_R4(13,15,26, 6)  x0 += K1; x1 += K2 + 1u;
    TF_R4(17,29,16,24)  x0 += K2; x1 += K0 + 2u;
    TF_R4(13,15,26, 6)  x0 += K0; x1 += K1 + 3u;
    TF_R4(17,29,16,24)  x0 += K1; x1 += K2 + 4u;
    TF_R4(13,15,26, 6)  x0 += K2; x1 += K0 + 5u;
#undef TF_R4
    uint32_t bits = x0 ^ x1;
    return __uint_as_float((bits >> 9) | 0x3f800000u) - 1.0f;
}

// ---------------- helpers ----------------
__device__ __forceinline__ void mma_f16(float (&c)[4], const uint32_t (&a)[4],
                                        const uint32_t (&b)[2]) {
    asm volatile(
        "mma.sync.aligned.m16n8k16.row.col.f32.f16.f16.f32 "
        "{%0,%1,%2,%3}, {%4,%5,%6,%7}, {%8,%9}, {%0,%1,%2,%3};"
        : "+f"(c[0]), "+f"(c[1]), "+f"(c[2]), "+f"(c[3])
        : "r"(a[0]), "r"(a[1]), "r"(a[2]), "r"(a[3]), "r"(b[0]), "r"(b[1]));
}
__device__ __forceinline__ void cpa16(uint32_t sa, const void* g) {
    asm volatile("cp.async.cg.shared.global [%0], [%1], 16;" :: "r"(sa), "l"(g));
}
__device__ __forceinline__ void cpa_commit() {
    asm volatile("cp.async.commit_group;");
}
template <int N>
__device__ __forceinline__ void cpa_wait() {
    asm volatile("cp.async.wait_group %0;" :: "n"(N));
}

// ============ fp16 pipelined GEMM: C = A @ B^T, A [M][K], B [N][K] halves ===
__device__ __forceinline__ void gemm_h(const __half* __restrict__ A,
                                       const __half* __restrict__ Bm,
                                       int K, int row0, int col0,
                                       float (&acc)[4][4][4]) {
    extern __shared__ float smf[];
    __half* sm = reinterpret_cast<__half*>(smf);
    const uint32_t sbase = (uint32_t)__cvta_generic_to_shared(sm);
    const int tid  = threadIdx.x;
    const int lane = tid & 31, warp = tid >> 5;
    const int wm = (warp & 1) * 64;
    const int wn = (warp >> 1) * 32;
    const int g = lane >> 2, t = lane & 3;

#pragma unroll
    for (int mi = 0; mi < 4; ++mi)
#pragma unroll
        for (int ni = 0; ni < 4; ++ni)
#pragma unroll
            for (int q = 0; q < 4; ++q) acc[mi][ni][q] = 0.0f;

    auto load_stage = [&](int s, int it) {
        const int k0 = it * HBK;
        const uint32_t st = sbase + (uint32_t)s * H_STAGE_BYTES;
#pragma unroll
        for (int p = 0; p < 2; ++p) {           // A: 128 rows x 4 chunks(8 halves)
            const int c  = tid + (p << 8);
            const int r  = c >> 2;
            const int ch = c & 3;
            cpa16(st + (uint32_t)(r * HSTRIDE + ch * 8) * 2u,
                  A + (size_t)(row0 + r) * K + k0 + ch * 8);
        }
#pragma unroll
        for (int p = 0; p < 2; ++p) {           // B: 128 rows x 4 chunks
            const int c  = tid + (p << 8);
            const int r  = c >> 2;
            const int ch = c & 3;
            cpa16(st + H_A_BYTES + (uint32_t)(r * HSTRIDE + ch * 8) * 2u,
                  Bm + (size_t)(col0 + r) * K + k0 + ch * 8);
        }
    };

    const int nk = K / HBK;
#pragma unroll
    for (int p = 0; p < HST - 1; ++p) { load_stage(p, p); cpa_commit(); }

    for (int i = 0; i < nk; ++i) {
        cpa_wait<HST - 2>();
        __syncthreads();
        const int ld = i + HST - 1;
        if (ld < nk) load_stage(ld & (HST - 1), ld);
        cpa_commit();

        const __half* As = sm + (size_t)(i & (HST - 1)) * (H_STAGE_BYTES / 2);
        const __half* Bs = As + BM * HSTRIDE;
#pragma unroll
        for (int ks = 0; ks < HBK / 16; ++ks) {
            const int k = ks << 4;
            uint32_t a[4][4];
#pragma unroll
            for (int mi = 0; mi < 4; ++mi) {
                const int m = wm + (mi << 4);
                a[mi][0] = *reinterpret_cast<const uint32_t*>(
                    &As[(m + g    ) * HSTRIDE + k + t * 2]);
                a[mi][1] = *reinterpret_cast<const uint32_t*>(
                    &As[(m + g + 8) * HSTRIDE + k + t * 2]);
                a[mi][2] = *reinterpret_cast<const uint32_t*>(
                    &As[(m + g    ) * HSTRIDE + k + 8 + t * 2]);
                a[mi][3] = *reinterpret_cast<const uint32_t*>(
                    &As[(m + g + 8) * HSTRIDE + k + 8 + t * 2]);
            }
            uint32_t b[4][2];
#pragma unroll
            for (int ni = 0; ni < 4; ++ni) {
                const int n = wn + (ni << 3);
                b[ni][0] = *reinterpret_cast<const uint32_t*>(
                    &Bs[(n + g) * HSTRIDE + k + t * 2]);
                b[ni][1] = *reinterpret_cast<const uint32_t*>(
                    &Bs[(n + g) * HSTRIDE + k + 8 + t * 2]);
            }
#pragma unroll
            for (int mi = 0; mi < 4; ++mi)
#pragma unroll
                for (int ni = 0; ni < 4; ++ni)
                    mma_f16(acc[mi][ni], a[mi], b[ni]);
        }
    }
    cpa_wait<0>();
}

// ---------------- kernel 0a: convert q/k/v fp32 -> fp16 ----------------
struct XArgs { const float* X[3]; };

__global__ __launch_bounds__(256)
void convert_x_kernel(XArgs xa) {
    const int z = blockIdx.z;
    const float* X = xa.X[z];
    __half* O = g_Xh[z];
    const size_t i = ((size_t)blockIdx.x * 256 + threadIdx.x) * 4;
    float4 v = *reinterpret_cast<const float4*>(X + i);
    __half2 h0 = __floats2half2_rn(v.x, v.y);
    __half2 h1 = __floats2half2_rn(v.z, v.w);
    *reinterpret_cast<__half2*>(O + i)     = h0;
    *reinterpret_cast<__half2*>(O + i + 2) = h1;
}

// ---------------- kernel 0b: W [K][N] -> Wt fp16 [N][K] ----------------
struct WArgs { const float* W[3]; };

__global__ __launch_bounds__(256)
void convert_w_kernel(WArgs wa) {
    __shared__ float tile[32][33];
    const int z = blockIdx.z;
    const float* W = wa.W[z];
    __half* Wt = g_Wth[z];
    const int bx = blockIdx.x * 32, by = blockIdx.y * 32;
    const int tx = threadIdx.x & 31, ty = (threadIdx.x >> 5) * 4;
#pragma unroll
    for (int i = 0; i < 4; ++i)
        tile[ty + i][tx] = W[(size_t)(by + ty + i) * D_ + bx + tx];
    __syncthreads();
#pragma unroll
    for (int i = 0; i < 4; ++i)
        Wt[(size_t)(bx + ty + i) * D_ + by + tx] = __float2half_rn(tile[tx][ty + i]);
}

// ---------------- kernel 1: fused Q/K/V projections (fp16 GEMM) ------------
struct ProjArgs { const float* b[3]; };

__global__ __launch_bounds__(256, 2)
void proj_kernel(ProjArgs pa) {
    const int z = blockIdx.z;
    const int row0 = blockIdx.y * BM, col0 = blockIdx.x * BN;
    float acc[4][4][4];
    gemm_h(g_Xh[z], g_Wth[z], D_, row0, col0, acc);

    const float* bias = pa.b[z];
    __half* C = (z == 0) ? g_Qh : (z == 1) ? g_Kh : g_Vh;
    const int tid = threadIdx.x, lane = tid & 31, warp = tid >> 5;
    const int rw0 = row0 + (warp & 1) * 64 + (lane >> 2);
    const int cw0 = col0 + (warp >> 1) * 32 + (lane & 3) * 2;
#pragma unroll
    for (int mi = 0; mi < 4; ++mi) {
#pragma unroll
        for (int ni = 0; ni < 4; ++ni) {
            const int c = cw0 + (ni << 3);
            const float bx = __ldg(bias + c), by = __ldg(bias + c + 1);
            const int r1 = rw0 + (mi << 4);
            __half2 h0 = __floats2half2_rn(acc[mi][ni][0] + bx, acc[mi][ni][1] + by);
            __half2 h1 = __floats2half2_rn(acc[mi][ni][2] + bx, acc[mi][ni][3] + by);
            *reinterpret_cast<__half2*>(C + (size_t)r1 * D_ + c)       = h0;
            *reinterpret_cast<__half2*>(C + (size_t)(r1 + 8) * D_ + c) = h1;
        }
    }
}

// ---------------- kernel 1b: transpose V (fp16) [b][s][d] -> [b][d][s] -----
__global__ __launch_bounds__(256)
void transpose_v_kernel() {
    __shared__ __half tile[64][65];
    const int b = blockIdx.z;
    const int s0 = blockIdx.x * 64, d0 = blockIdx.y * 64;
    const __half* in = g_Vh + (size_t)b * S_ * D_;
    __half* out = g_Vth + (size_t)b * D_ * S_;
    const int tid = threadIdx.x;
#pragma unroll
    for (int i = 0; i < 16; ++i) {
        const int idx = tid + (i << 8);
        const int r = idx >> 6, c = idx & 63;
        tile[r][c] = in[(size_t)(s0 + r) * D_ + d0 + c];
    }
    __syncthreads();
#pragma unroll
    for (int i = 0; i < 16; ++i) {
        const int idx = tid + (i << 8);
        const int r = idx >> 6, c = idx & 63;
        out[(size_t)(d0 + r) * S_ + s0 + c] = tile[c][r];
    }
}

// ------- kernel 2: scores = (Q K^T)/sqrt(D) + pre-softmax dropout (fp32 out)
__global__ __launch_bounds__(256, 2)
void scores_kernel() {
    const int bz = blockIdx.z;
    const int row0 = blockIdx.y * BM, col0 = blockIdx.x * BN;
    float acc[4][4][4];
    gemm_h(g_Qh + (size_t)bz * S_ * D_, g_Kh + (size_t)bz * S_ * D_,
           D_, row0, col0, acc);

    float* C = g_S + (size_t)bz * S_ * S_;
    const int tid = threadIdx.x, lane = tid & 31, warp = tid >> 5;
    const int rw0 = row0 + (warp & 1) * 64 + (lane >> 2);
    const int cw0 = col0 + (warp >> 1) * 32 + (lane & 3) * 2;
    const float sc = 0.03608439182435161f;  // 1/sqrt(768)
#pragma unroll
    for (int mi = 0; mi < 4; ++mi) {
#pragma unroll
        for (int rr = 0; rr < 2; ++rr) {
            const int r = rw0 + (mi << 4) + (rr << 3);
            const uint32_t ib = ((uint32_t)bz * S_ + (uint32_t)r) * (uint32_t)S_;
#pragma unroll
            for (int ni = 0; ni < 4; ++ni) {
                const int c = cw0 + (ni << 3);
                const float v0 = acc[mi][ni][rr * 2 + 0] * sc;
                const float v1 = acc[mi][ni][rr * 2 + 1] * sc;
                const float u0 = tf_uniform(ib + (uint32_t)c);
                const float u1 = tf_uniform(ib + (uint32_t)c + 1u);
                float2 o;
                o.x = (u0 < 0.8f) ? v0 * 1.25f : 0.0f;
                o.y = (u1 < 0.8f) ? v1 * 1.25f : 0.0f;
                *reinterpret_cast<float2*>(C + (size_t)r * S_ + c) = o;
            }
        }
    }
}

// ------ kernel 3: softmax over k, post-softmax mask, write fp16 probs ------
__global__ __launch_bounds__(256)
void softmax_mask_kernel(const int* __restrict__ mask) {
    const int row = blockIdx.x;
    const float* srow = g_S + (size_t)row * S_;
    __half* prow = g_P + (size_t)row * S_;
    const int* mrow = mask + (size_t)row * S_;
    const int t = threadIdx.x;
    __shared__ float red[8];

    float4 v4[2];
    v4[0] = *reinterpret_cast<const float4*>(srow + (t << 2));
    v4[1] = *reinterpret_cast<const float4*>(srow + 1024 + (t << 2));
    float* v = reinterpret_cast<float*>(v4);

    float mx = v[0];
#pragma unroll
    for (int i = 1; i < 8; ++i) mx = fmaxf(mx, v[i]);
#pragma unroll
    for (int o = 16; o > 0; o >>= 1)
        mx = fmaxf(mx, __shfl_xor_sync(0xffffffffu, mx, o));
    if ((t & 31) == 0) red[t >> 5] = mx;
    __syncthreads();
    if (t < 32) {
        float m2 = (t < 8) ? red[t] : -3.4e38f;
#pragma unroll
        for (int o = 4; o > 0; o >>= 1)
            m2 = fmaxf(m2, __shfl_xor_sync(0xffffffffu, m2, o));
        if (t == 0) red[0] = m2;
    }
    __syncthreads();
    mx = red[0];
    __syncthreads();

    float sum = 0.0f;
#pragma unroll
    for (int i = 0; i < 8; ++i) { v[i] = __expf(v[i] - mx); sum += v[i]; }
#pragma unroll
    for (int o = 16; o > 0; o >>= 1)
        sum += __shfl_xor_sync(0xffffffffu, sum, o);
    if ((t & 31) == 0) red[t >> 5] = sum;
    __syncthreads();
    if (t < 32) {
        float s2 = (t < 8) ? red[t] : 0.0f;
#pragma unroll
        for (int o = 4; o > 0; o >>= 1)
            s2 += __shfl_xor_sync(0xffffffffu, s2, o);
        if (t == 0) red[0] = s2;
    }
    __syncthreads();
    const float inv = 1.0f / red[0];

    int4 m4[2];
    m4[0] = *reinterpret_cast<const int4*>(mrow + (t << 2));
    m4[1] = *reinterpret_cast<const int4*>(mrow + 1024 + (t << 2));
    const int* m = reinterpret_cast<const int*>(m4);
#pragma unroll
    for (int i = 0; i < 8; ++i)
        v[i] = (m[i] == 0) ? 1e-9f : v[i] * inv;
#pragma unroll
    for (int p = 0; p < 2; ++p) {
        __half2 h0 = __floats2half2_rn(v[p * 4 + 0], v[p * 4 + 1]);
        __half2 h1 = __floats2half2_rn(v[p * 4 + 2], v[p * 4 + 3]);
        const int base = p * 1024 + (t << 2);
        *reinterpret_cast<__half2*>(prow + base)     = h0;
        *reinterpret_cast<__half2*>(prow + base + 2) = h1;
    }
}

// -------- kernel 4: out = att @ V  (A = probs fp16, B = Vt fp16 BTRANS) ----
__global__ __launch_bounds__(256, 2)
void out_kernel(float* __restrict__ Og) {
    const int bz = blockIdx.z;
    const int row0 = blockIdx.y * BM, col0 = blockIdx.x * BN;
    float acc[4][4][4];
    gemm_h(g_P + (size_t)bz * S_ * S_, g_Vth + (size_t)bz * D_ * S_,
           S_, row0, col0, acc);

    float* C = Og + (size_t)bz * S_ * D_;
    const int tid = threadIdx.x, lane = tid & 31, warp = tid >> 5;
    const int rw0 = row0 + (warp & 1) * 64 + (lane >> 2);
    const int cw0 = col0 + (warp >> 1) * 32 + (lane & 3) * 2;
#pragma unroll
    for (int mi = 0; mi < 4; ++mi) {
#pragma unroll
        for (int ni = 0; ni < 4; ++ni) {
            const int c = cw0 + (ni << 3);
            const int r1 = rw0 + (mi << 4);
            float2 o0 = make_float2(acc[mi][ni][0], acc[mi][ni][1]);
            float2 o1 = make_float2(acc[mi][ni][2], acc[mi][ni][3]);
            *reinterpret_cast<float2*>(C + (size_t)r1 * D_ + c)       = o0;
            *reinterpret_cast<float2*>(C + (size_t)(r1 + 8) * D_ + c) = o1;
        }
    }
}

// ---------------- launch ----------------
extern "C" void kernel_launch(void* const* d_in, const int* in_sizes, int n_in,
                              void* d_out, int out_size) {
    const int* mask = (const int*)d_in[3];

    XArgs xa;
    xa.X[0] = (const float*)d_in[0];
    xa.X[1] = (const float*)d_in[1];
    xa.X[2] = (const float*)d_in[2];

    WArgs wa;
    wa.W[0] = (const float*)d_in[4];
    wa.W[1] = (const float*)d_in[6];
    wa.W[2] = (const float*)d_in[8];

    ProjArgs pa;
    pa.b[0] = (const float*)d_in[5];
    pa.b[1] = (const float*)d_in[7];
    pa.b[2] = (const float*)d_in[9];

    const int smem_h = H_STAGE_BYTES * HST;          // 81920 B
    cudaFuncSetAttribute(proj_kernel,
        cudaFuncAttributeMaxDynamicSharedMemorySize, smem_h);
    cudaFuncSetAttribute(scores_kernel,
        cudaFuncAttributeMaxDynamicSharedMemorySize, smem_h);
    cudaFuncSetAttribute(out_kernel,
        cudaFuncAttributeMaxDynamicSharedMemorySize, smem_h);

    dim3 blk(256);

    dim3 gcx((M1 * D_) / 1024, 1, 3);
    convert_x_kernel<<<gcx, blk>>>(xa);

    dim3 gcw(D_ / 32, D_ / 32, 3);
    convert_w_kernel<<<gcw, blk>>>(wa);

    dim3 gproj(D_ / BN, M1 / BM, 3);
    proj_kernel<<<gproj, blk, smem_h>>>(pa);

    dim3 gtv(S_ / 64, D_ / 64, B_);
    transpose_v_kernel<<<gtv, blk>>>();

    dim3 gsc(S_ / BN, S_ / BM, B_);
    scores_kernel<<<gsc, blk, smem_h>>>();

    softmax_mask_kernel<<<M1, blk>>>(mask);

    dim3 gout(D_ / BN, S_ / BM, B_);
    out_kernel<<<gout, blk, smem_h>>>((float*)d_out);
}